// round 11
// baseline (speedup 1.0000x reference)
#include <cuda_runtime.h>
#include <math.h>

#define BB 8
#define CC 256
#define TT 16
#define HWN 1024
#define CR 16

// ---------------- scratch (device globals; no allocation) -------------------
__device__ float g_sp[BB * CC * HWN];   // spatial pooled mean  [b, c, hw]
__device__ float g_tp[BB * CC * TT];    // temporal pooled mean [b, c, t]
__device__ float g_cp[BB * CC];         // channel pooled mean  [b, c]
__device__ float g_comb[BB * CC * TT];  // temporal_att * channel_att
__device__ float g_att[BB * CC * HWN];  // spatial attention    [b, c, hw]

__device__ __forceinline__ float sigmoidf(float a) {
    return 1.0f / (1.0f + __expf(-a));
}

// ---------------- K1: pooling (R1 proven: 27.6us, 63.5% DRAM) ----------------
// one block per (b,c); 256 threads; float4 loads.
__global__ void __launch_bounds__(256) pool_kernel(const float* __restrict__ x) {
    const int bc  = blockIdx.x;
    const int tid = threadIdx.x;
    const float4* xb = (const float4*)(x + (size_t)bc * (TT * HWN));

    float4 sp = make_float4(0.f, 0.f, 0.f, 0.f);
    float tpar[TT];

#pragma unroll
    for (int t = 0; t < TT; t++) {
        float4 v = xb[t * (HWN / 4) + tid];
        sp.x += v.x; sp.y += v.y; sp.z += v.z; sp.w += v.w;
        tpar[t] = (v.x + v.y) + (v.z + v.w);
    }

    float4 spo;
    spo.x = sp.x * (1.f / TT); spo.y = sp.y * (1.f / TT);
    spo.z = sp.z * (1.f / TT); spo.w = sp.w * (1.f / TT);
    ((float4*)(g_sp + (size_t)bc * HWN))[tid] = spo;

    __shared__ float wsum[8][TT];
    const int lane = tid & 31;
    const int wid  = tid >> 5;
#pragma unroll
    for (int t = 0; t < TT; t++) {
        float s = tpar[t];
#pragma unroll
        for (int off = 16; off > 0; off >>= 1)
            s += __shfl_down_sync(0xffffffffu, s, off);
        if (lane == 0) wsum[wid][t] = s;
    }
    __syncthreads();
    if (tid < TT) {
        float s = 0.f;
#pragma unroll
        for (int w = 0; w < 8; w++) s += wsum[w][tid];
        g_tp[bc * TT + tid] = s * (1.f / HWN);
        wsum[0][tid] = s;
    }
    __syncthreads();
    if (tid == 0) {
        float tot = 0.f;
#pragma unroll
        for (int t = 0; t < TT; t++) tot += wsum[0][t];
        g_cp[bc] = tot * (1.f / (TT * HWN));
    }
}

// ---------------- K2: middle — spatial att (bid<1024) + small SE -------------
// grid = 1152, 256 threads, ~17KB smem.
// att block = (b, 8-hw window); thread = (c-group of 8 channels, hw lane).
__global__ void __launch_bounds__(256) attmid_kernel(
        const float* __restrict__ ws1, const float* __restrict__ bs1,
        const float* __restrict__ ws2, const float* __restrict__ bs2,
        const float* __restrict__ wt1, const float* __restrict__ bt1,
        const float* __restrict__ wt2, const float* __restrict__ bt2,
        const float* __restrict__ wc1, const float* __restrict__ bc1,
        const float* __restrict__ wc2, const float* __restrict__ bc2) {
    __shared__ float sm[32 * CR * 8 + CR * 8];   // stage[4096] + hidf[128]
    const int tid = threadIdx.x;

    if (blockIdx.x < 1024) {
        float* stage = sm;              // [c8][r][hwl]
        float* hidf  = sm + 32 * CR * 8; // [r][hwl]

        const int b   = blockIdx.x >> 7;
        const int hw0 = (blockIdx.x & 127) * 8;
        const int c8  = tid >> 3;       // 0..31 -> channels c8*8..c8*8+7
        const int hwl = tid & 7;        // 0..7

        // phase 1: partial hidden over this thread's 8 channels
        float ph[CR];
#pragma unroll
        for (int r = 0; r < CR; r++) ph[r] = 0.f;

        const float* spb = g_sp + (size_t)(b * CC) * HWN + hw0 + hwl;
#pragma unroll
        for (int i = 0; i < 8; i++) {
            const int c = c8 * 8 + i;
            const float v = spb[(size_t)c * HWN];
#pragma unroll
            for (int r = 0; r < CR; r++)
                ph[r] = fmaf(__ldg(&ws1[r * CC + c]), v, ph[r]);
        }
#pragma unroll
        for (int r = 0; r < CR; r++) stage[(c8 * CR + r) * 8 + hwl] = ph[r];
        __syncthreads();

        // phase 2: reduce 32 partials -> hidden (+bias, ReLU); 128 threads
        if (tid < CR * 8) {
            const int r  = tid >> 3;
            const int hl = tid & 7;
            float s = bs1[r];
#pragma unroll
            for (int g = 0; g < 32; g++) s += stage[(g * CR + r) * 8 + hl];
            hidf[r * 8 + hl] = fmaxf(s, 0.f);
        }
        __syncthreads();

        // phase 3: att for this thread's 8 channels
        float hv[CR];
#pragma unroll
        for (int r = 0; r < CR; r++) hv[r] = hidf[r * 8 + hwl];

        float* attb = g_att + (size_t)(b * CC) * HWN + hw0 + hwl;
#pragma unroll
        for (int i = 0; i < 8; i++) {
            const int c = c8 * 8 + i;
            const float4* wr = (const float4*)(ws2 + c * CR);
            float a = __ldg(&bs2[c]);
            const float4 w0 = __ldg(wr + 0);
            a = fmaf(w0.x, hv[0], a);  a = fmaf(w0.y, hv[1], a);
            a = fmaf(w0.z, hv[2], a);  a = fmaf(w0.w, hv[3], a);
            const float4 w1 = __ldg(wr + 1);
            a = fmaf(w1.x, hv[4], a);  a = fmaf(w1.y, hv[5], a);
            a = fmaf(w1.z, hv[6], a);  a = fmaf(w1.w, hv[7], a);
            const float4 w2 = __ldg(wr + 2);
            a = fmaf(w2.x, hv[8],  a); a = fmaf(w2.y, hv[9],  a);
            a = fmaf(w2.z, hv[10], a); a = fmaf(w2.w, hv[11], a);
            const float4 w3 = __ldg(wr + 3);
            a = fmaf(w3.x, hv[12], a); a = fmaf(w3.y, hv[13], a);
            a = fmaf(w3.z, hv[14], a); a = fmaf(w3.w, hv[15], a);
            attb[(size_t)c * HWN] = sigmoidf(a);
        }
    } else {
        // ---- temporal + channel SE -> g_comb (R2 proven design) ----
        const int idx = blockIdx.x - 1024;   // 0..127
        const int b   = idx >> 4;
        const int t   = idx & 15;

        float* pt   = sm;          // [256]
        float* pc   = sm + 256;    // [256]
        float* hids = sm + 512;    // [32]

        pt[tid] = g_tp[(b * CC + tid) * TT + t];
        pc[tid] = g_cp[b * CC + tid];
        __syncthreads();

        if (tid < CR) {
            float s = bt1[tid];
            for (int c = 0; c < CC; c++) s = fmaf(wt1[tid * CC + c], pt[c], s);
            hids[tid] = fmaxf(s, 0.f);
        } else if (tid < 2 * CR) {
            const int r = tid - CR;
            float s = bc1[r];
            for (int c = 0; c < CC; c++) s = fmaf(wc1[r * CC + c], pc[c], s);
            hids[tid] = fmaxf(s, 0.f);
        }
        __syncthreads();

        float at = bt2[tid];
        float ac = bc2[tid];
#pragma unroll
        for (int r = 0; r < CR; r++) {
            at = fmaf(wt2[tid * CR + r], hids[r],      at);
            ac = fmaf(wc2[tid * CR + r], hids[CR + r], ac);
        }
        g_comb[(b * CC + tid) * TT + t] = sigmoidf(at) * sigmoidf(ac);
    }
}

// ---------------- K3: pure streaming apply (proven: 38.4us, 74% DRAM) --------
// one block per (b,c); 256 threads
__global__ void __launch_bounds__(256) apply_kernel(const float* __restrict__ x,
                                                    float* __restrict__ out) {
    const int bc  = blockIdx.x;
    const int tid = threadIdx.x;

    __shared__ float combs[TT];
    if (tid < TT) combs[tid] = g_comb[bc * TT + tid];

    const float4 a = ((const float4*)(g_att + (size_t)bc * HWN))[tid];
    __syncthreads();

    const float4* xp = (const float4*)(x + (size_t)bc * (TT * HWN));
    float4* op       = (float4*)(out + (size_t)bc * (TT * HWN));

#pragma unroll
    for (int t = 0; t < TT; t++) {
        const float s = combs[t];
        float4 v = xp[t * (HWN / 4) + tid];
        v.x = v.x * a.x * s;
        v.y = v.y * a.y * s;
        v.z = v.z * a.z * s;
        v.w = v.w * a.w * s;
        op[t * (HWN / 4) + tid] = v;
    }
}

// ---------------- launch -----------------------------------------------------
extern "C" void kernel_launch(void* const* d_in, const int* in_sizes, int n_in,
                              void* d_out, int out_size) {
    const float* x   = (const float*)d_in[0];
    const float* ws1 = (const float*)d_in[1];
    const float* bs1 = (const float*)d_in[2];
    const float* ws2 = (const float*)d_in[3];
    const float* bs2 = (const float*)d_in[4];
    const float* wt1 = (const float*)d_in[5];
    const float* bt1 = (const float*)d_in[6];
    const float* wt2 = (const float*)d_in[7];
    const float* bt2 = (const float*)d_in[8];
    const float* wc1 = (const float*)d_in[9];
    const float* bc1 = (const float*)d_in[10];
    const float* wc2 = (const float*)d_in[11];
    const float* bc2 = (const float*)d_in[12];
    float* out = (float*)d_out;

    pool_kernel<<<BB * CC, 256>>>(x);
    attmid_kernel<<<1152, 256>>>(ws1, bs1, ws2, bs2,
                                 wt1, bt1, wt2, bt2,
                                 wc1, bc1, wc2, bc2);
    apply_kernel<<<BB * CC, 256>>>(x, out);
}